// round 9
// baseline (speedup 1.0000x reference)
#include <cuda_runtime.h>
#include <cstdint>

#define N_LEVELS 16
#define TABLE_SIZE (1u << 19)
#define TMASK (TABLE_SIZE - 1u)
#define P1 2654435761u
#define P2 805459861u
#define BLOCK 128
#define PTS_PER_THREAD 2
#define MAXN 2000000
#define GBITS 6
#define GRES (1 << GBITS)            // 64 cells per dim
#define NCELLS (GRES * GRES * GRES)  // 262144
#define S1_T 1024
#define S1_B (NCELLS / S1_T)         // 256

using ull = unsigned long long;

__device__ __forceinline__ ull pack2(float lo, float hi) {
    ull r; asm("mov.b64 %0, {%1, %2};" : "=l"(r) : "f"(lo), "f"(hi)); return r;
}
__device__ __forceinline__ void unpack2(ull v, float& lo, float& hi) {
    asm("mov.b64 {%0, %1}, %2;" : "=f"(lo), "=f"(hi) : "l"(v));
}
__device__ __forceinline__ ull fma2(ull a, ull b, ull c) {
    ull d; asm("fma.rn.f32x2 %0, %1, %2, %3;" : "=l"(d) : "l"(a), "l"(b), "l"(c)); return d;
}

// ---- static scratch (no allocation) ----
__device__ int    d_hist[NCELLS];
__device__ int    d_offs[NCELLS];
__device__ int    d_bsum[S1_B];
__device__ int    d_boff[S1_B];
__device__ float4 d_xs[MAXN];

__device__ __forceinline__ unsigned part1by2(unsigned v) {
    v &= 0x3FFu;
    v = (v | (v << 16)) & 0x030000FFu;
    v = (v | (v << 8))  & 0x0300F00Fu;
    v = (v | (v << 4))  & 0x030C30C3u;
    v = (v | (v << 2))  & 0x09249249u;
    return v;
}

__device__ __forceinline__ int cell_of(float x0, float x1, float x2) {
    unsigned cx = min(GRES - 1, (int)(x0 * (float)GRES));
    unsigned cy = min(GRES - 1, (int)(x1 * (float)GRES));
    unsigned cz = min(GRES - 1, (int)(x2 * (float)GRES));
    return (int)((part1by2(cx) << 2) | (part1by2(cy) << 1) | part1by2(cz));
}

__global__ void k_zero() {
    int i = blockIdx.x * blockDim.x + threadIdx.x;
    if (i < NCELLS) d_hist[i] = 0;
}

__global__ void k_hist(const float* __restrict__ x, int n) {
    int i = blockIdx.x * blockDim.x + threadIdx.x;
    if (i >= n) return;
    float x0 = x[3 * i + 0] * 0.5f + 0.5f;
    float x1 = x[3 * i + 1] * 0.5f + 0.5f;
    float x2 = x[3 * i + 2] * 0.5f + 0.5f;
    atomicAdd(&d_hist[cell_of(x0, x1, x2)], 1);
}

__global__ void k_scan1() {
    __shared__ int sc[S1_T];
    const int t = threadIdx.x;
    const int g = blockIdx.x * S1_T + t;
    const int v = d_hist[g];
    sc[t] = v;
    __syncthreads();
    #pragma unroll
    for (int d = 1; d < S1_T; d <<= 1) {
        int u = (t >= d) ? sc[t - d] : 0;
        __syncthreads();
        sc[t] += u;
        __syncthreads();
    }
    d_offs[g] = sc[t] - v;
    if (t == S1_T - 1) d_bsum[blockIdx.x] = sc[t];
}

__global__ void k_scan2() {
    __shared__ int sc[S1_B];
    const int t = threadIdx.x;
    const int v = d_bsum[t];
    sc[t] = v;
    __syncthreads();
    #pragma unroll
    for (int d = 1; d < S1_B; d <<= 1) {
        int u = (t >= d) ? sc[t - d] : 0;
        __syncthreads();
        sc[t] += u;
        __syncthreads();
    }
    d_boff[t] = sc[t] - v;
}

__global__ void k_scan3() {
    const int g = blockIdx.x * S1_T + threadIdx.x;
    d_offs[g] += d_boff[blockIdx.x];
}

__global__ void k_scatter(const float* __restrict__ x, int n) {
    int i = blockIdx.x * blockDim.x + threadIdx.x;
    if (i >= n) return;
    float x0 = x[3 * i + 0] * 0.5f + 0.5f;
    float x1 = x[3 * i + 1] * 0.5f + 0.5f;
    float x2 = x[3 * i + 2] * 0.5f + 0.5f;
    int pos = atomicAdd(&d_offs[cell_of(x0, x1, x2)], 1);
    d_xs[pos] = make_float4(x0, x1, x2, __int_as_float(i));
}

// encode one point -> a[32]
__device__ __forceinline__ void encode_point(float x0, float x1, float x2,
                                             const float* __restrict__ tables,
                                             const float* __restrict__ sRes,
                                             float* a)
{
    #pragma unroll
    for (int L = 0; L < N_LEVELS; L++) {
        const float r = sRes[L];
        const float px = x0 * r, py = x1 * r, pz = x2 * r;
        const float fx = floorf(px), fy = floorf(py), fz = floorf(pz);
        const float wx = px - fx, wy = py - fy, wz = pz - fz;
        const unsigned cx = (unsigned)fx, cy = (unsigned)fy, cz = (unsigned)fz;

        const unsigned hx0 = cx,        hx1 = cx + 1u;
        const unsigned hy0 = cy * P1,   hy1 = (cy + 1u) * P1;
        const unsigned hz0 = cz * P2,   hz1 = (cz + 1u) * P2;

        const float2* __restrict__ tab =
            reinterpret_cast<const float2*>(tables) + (size_t)L * TABLE_SIZE;

        const float ox = 1.0f - wx, oy = 1.0f - wy, oz = 1.0f - wz;

        float ax = 0.0f, ay = 0.0f;
        #pragma unroll
        for (int c = 0; c < 8; c++) {
            const unsigned h = ((c & 1) ? hx1 : hx0)
                             ^ ((c & 2) ? hy1 : hy0)
                             ^ ((c & 4) ? hz1 : hz0);
            const unsigned idx = h & TMASK;
            const float2 t = __ldg(&tab[idx]);
            const float wc = ((c & 1) ? wx : ox)
                           * ((c & 2) ? wy : oy)
                           * ((c & 4) ? wz : oz);
            ax = fmaf(wc, t.x, ax);
            ay = fmaf(wc, t.y, ay);
        }
        a[2 * L + 0] = ax;
        a[2 * L + 1] = ay;
    }
}

__global__ __launch_bounds__(BLOCK, 2)
void hashgrid_mlp_kernel(const float* __restrict__ tables,
                         const float* __restrict__ resolutions,
                         const float* __restrict__ W1, const float* __restrict__ b1,
                         const float* __restrict__ W2, const float* __restrict__ b2,
                         const float* __restrict__ W3, const float* __restrict__ b3,
                         float* __restrict__ out, int n)
{
    __shared__ __align__(16) float sW1[32 * 64];
    __shared__ __align__(16) float sW2[64 * 64];
    __shared__ __align__(16) float sB1[64];
    __shared__ __align__(16) float sB2[64];
    __shared__ __align__(16) float sW3[64];
    __shared__ float sRes[16];
    __shared__ float sB3;

    const int tid = threadIdx.x;
    for (int i = tid; i < 32 * 64; i += BLOCK) sW1[i] = W1[i];
    for (int i = tid; i < 64 * 64; i += BLOCK) sW2[i] = W2[i];
    if (tid < 64) { sB1[tid] = b1[tid]; sB2[tid] = b2[tid]; sW3[tid] = W3[tid]; }
    if (tid < 16) sRes[tid] = resolutions[tid];
    if (tid == 0) sB3 = b3[0];
    __syncthreads();

    const int base = (blockIdx.x * BLOCK + tid) * PTS_PER_THREAD;
    if (base >= n) return;
    const bool haveB = (base + 1) < n;

    // two Morton-adjacent sorted points
    const float4 xiA = d_xs[base];
    const float4 xiB = haveB ? d_xs[base + 1] : xiA;
    const int oiA = __float_as_int(xiA.w);
    const int oiB = __float_as_int(xiB.w);

    float aA[32], aB[32];
    encode_point(xiA.x, xiA.y, xiA.z, tables, sRes, aA);
    encode_point(xiB.x, xiB.y, xiB.z, tables, sRes, aB);

    // ---- layer 1 (dual point): one weight load feeds both points ----
    ull hA[32], hB[32];
    #pragma unroll
    for (int j = 0; j < 32; j++) {
        const ull b = *reinterpret_cast<const ull*>(&sB1[2 * j]);
        hA[j] = b; hB[j] = b;
    }
    #pragma unroll
    for (int i = 0; i < 32; i++) {
        const ull apA = pack2(aA[i], aA[i]);
        const ull apB = pack2(aB[i], aB[i]);
        const ull* wrow = reinterpret_cast<const ull*>(&sW1[i * 64]);
        #pragma unroll
        for (int j = 0; j < 32; j += 2) {
            const ulonglong2 w = *reinterpret_cast<const ulonglong2*>(&wrow[j]);
            hA[j + 0] = fma2(apA, w.x, hA[j + 0]);
            hA[j + 1] = fma2(apA, w.y, hA[j + 1]);
            hB[j + 0] = fma2(apB, w.x, hB[j + 0]);
            hB[j + 1] = fma2(apB, w.y, hB[j + 1]);
        }
    }

    // ---- layer 2 (dual point, two halves) fused with layer 3 ----
    float r3A = sB3, r3B = sB3;
    #pragma unroll
    for (int half = 0; half < 2; half++) {
        const int cb = 32 * half;
        ull accA[16], accB[16];
        #pragma unroll
        for (int jj = 0; jj < 16; jj++) {
            const ull b = *reinterpret_cast<const ull*>(&sB2[cb + 2 * jj]);
            accA[jj] = b; accB[jj] = b;
        }

        #pragma unroll
        for (int i2 = 0; i2 < 32; i2++) {
            float loA, hiA, loB, hiB;
            unpack2(hA[i2], loA, hiA);
            unpack2(hB[i2], loB, hiB);
            loA = fmaxf(loA, 0.0f); hiA = fmaxf(hiA, 0.0f);
            loB = fmaxf(loB, 0.0f); hiB = fmaxf(hiB, 0.0f);
            const ull plA = pack2(loA, loA), phA = pack2(hiA, hiA);
            const ull plB = pack2(loB, loB), phB = pack2(hiB, hiB);
            const ull* w0 = reinterpret_cast<const ull*>(&sW2[(2 * i2 + 0) * 64 + cb]);
            const ull* w1 = reinterpret_cast<const ull*>(&sW2[(2 * i2 + 1) * 64 + cb]);
            #pragma unroll
            for (int jj = 0; jj < 16; jj += 2) {
                const ulonglong2 wa = *reinterpret_cast<const ulonglong2*>(&w0[jj]);
                accA[jj + 0] = fma2(plA, wa.x, accA[jj + 0]);
                accA[jj + 1] = fma2(plA, wa.y, accA[jj + 1]);
                accB[jj + 0] = fma2(plB, wa.x, accB[jj + 0]);
                accB[jj + 1] = fma2(plB, wa.y, accB[jj + 1]);
            }
            #pragma unroll
            for (int jj = 0; jj < 16; jj += 2) {
                const ulonglong2 wb = *reinterpret_cast<const ulonglong2*>(&w1[jj]);
                accA[jj + 0] = fma2(phA, wb.x, accA[jj + 0]);
                accA[jj + 1] = fma2(phA, wb.y, accA[jj + 1]);
                accB[jj + 0] = fma2(phB, wb.x, accB[jj + 0]);
                accB[jj + 1] = fma2(phB, wb.y, accB[jj + 1]);
            }
        }
        #pragma unroll
        for (int jj = 0; jj < 16; jj++) {
            float a0, a1;
            const float w3lo = sW3[cb + 2 * jj + 0];
            const float w3hi = sW3[cb + 2 * jj + 1];
            unpack2(accA[jj], a0, a1);
            r3A = fmaf(fmaxf(a0, 0.0f), w3lo, r3A);
            r3A = fmaf(fmaxf(a1, 0.0f), w3hi, r3A);
            unpack2(accB[jj], a0, a1);
            r3B = fmaf(fmaxf(a0, 0.0f), w3lo, r3B);
            r3B = fmaf(fmaxf(a1, 0.0f), w3hi, r3B);
        }
    }

    out[oiA] = r3A;
    if (haveB) out[oiB] = r3B;
}

extern "C" void kernel_launch(void* const* d_in, const int* in_sizes, int n_in,
                              void* d_out, int out_size)
{
    const float* x    = (const float*)d_in[0];
    const float* tabs = (const float*)d_in[1];
    const float* res  = (const float*)d_in[2];
    const float* W1   = (const float*)d_in[3];
    const float* b1   = (const float*)d_in[4];
    const float* W2   = (const float*)d_in[5];
    const float* b2   = (const float*)d_in[6];
    const float* W3   = (const float*)d_in[7];
    const float* b3   = (const float*)d_in[8];
    float* out = (float*)d_out;

    const int n = in_sizes[0] / 3;

    k_zero<<<(NCELLS + 1023) / 1024, 1024>>>();
    k_hist<<<(n + 255) / 256, 256>>>(x, n);
    k_scan1<<<S1_B, S1_T>>>();
    k_scan2<<<1, S1_B>>>();
    k_scan3<<<S1_B, S1_T>>>();
    k_scatter<<<(n + 255) / 256, 256>>>(x, n);

    const int ptsPerBlock = BLOCK * PTS_PER_THREAD;
    const int grid = (n + ptsPerBlock - 1) / ptsPerBlock;
    hashgrid_mlp_kernel<<<grid, BLOCK>>>(tabs, res, W1, b1, W2, b2, W3, b3, out, n);
}